// round 9
// baseline (speedup 1.0000x reference)
#include <cuda_runtime.h>
#include <stdint.h>

#define DIM_IN 16
#define CH 128
#define DIM_OUT 99
#define MAX_NNZ 512
#define MAX_PADDED 1024
#define NPAIRS ((DIM_OUT + 1) / 2)   // 50
#define EPB 2
#define THREADS (EPB * 64)

// 8-byte term: .x = ox | (oy<<16) (u16 byte offsets into 8 KB row block), .y = cg
__device__ uint2 g_terms[MAX_PADDED];
__device__ uint2 g_pairs[NPAIRS];
// pair: .x = kA | (kB<<16) ; .y = n | (oA<<8) | (oB<<16)

__constant__ uint2 c_terms[MAX_PADDED];
__constant__ uint2 c_pairs[NPAIRS];

// ---------------------------------------------------------------------------
// Prep: CSR-sort terms by mu3 (stable), sort rows by count desc (stable),
// pair adjacent rows, zero-pad shorter row to pair max. All deterministic.
// ---------------------------------------------------------------------------
__global__ void prep_kernel(const int* __restrict__ mu1,
                            const int* __restrict__ mu2,
                            const int* __restrict__ mu3,
                            const float* __restrict__ cg,
                            int nnz)
{
    __shared__ int   sm3[MAX_NNZ];
    __shared__ uint2 st8[MAX_NNZ];       // CSR-sorted compact terms
    __shared__ int   start[DIM_OUT + 1]; // row starts
    __shared__ int   cnt[DIM_OUT + 1];   // row counts
    __shared__ int   order[DIM_OUT + 1];
    __shared__ int   pkA[NPAIRS], pmeta[NPAIRS];
    int t = threadIdx.x;

    if (t < DIM_OUT + 1) { start[t] = 0; cnt[t] = 0; }
    __syncthreads();

    for (int k = t; k < nnz; k += blockDim.x) {
        int m = mu3[k];
        sm3[k] = m;
        atomicAdd(&cnt[m], 1);
    }
    __syncthreads();

    if (t == 0) {
        int s = 0;
        for (int o = 0; o < DIM_OUT; o++) { start[o] = s; s += cnt[o]; }
        start[DIM_OUT] = s;
    }
    __syncthreads();

    // stable scatter into CSR (rank = #earlier terms with same mu3)
    for (int k = t; k < nnz; k += blockDim.x) {
        int m = sm3[k];
        int rank = 0;
        for (int j = 0; j < k; j++) rank += (sm3[j] == m);
        unsigned int ox = (unsigned int)mu1[k] * (CH * 4u);
        unsigned int oy = (unsigned int)mu2[k] * (CH * 4u);
        uint2 tm;
        tm.x = ox | (oy << 16);
        tm.y = __float_as_uint(cg[k]);
        st8[start[m] + rank] = tm;
    }
    __syncthreads();

    // thread0: counting sort rows by count (desc, stable by row id); pair up
    if (t == 0) {
        int idx = 0;
        for (int c = 63; c >= 0; c--)
            for (int o = 0; o < DIM_OUT; o++)
                if (cnt[o] == c) order[idx++] = o;
        int base = 0;
        for (int p = 0; p < NPAIRS; p++) {
            int rA = order[2 * p];
            int rB = (2 * p + 1 < DIM_OUT) ? order[2 * p + 1] : rA;
            int n  = cnt[rA] > cnt[rB] ? cnt[rA] : cnt[rB];
            pkA[p]   = base;
            pmeta[p] = n | (rA << 8) | (rB << 16);
            base += 2 * n;
        }
    }
    __syncthreads();

    // parallel emit of padded term table + pair descriptors
    for (int p = t; p < NPAIRS; p += blockDim.x) {
        int meta = pmeta[p];
        int n  = meta & 0xFF;
        int rA = (meta >> 8) & 0xFF;
        int rB = (meta >> 16) & 0xFF;
        int kA = pkA[p];
        int kB = kA + n;
        int sA = start[rA], cA = cnt[rA];
        int sB = start[rB], cB = cnt[rB];
        uint2 zero; zero.x = 0u; zero.y = 0u;   // cg = +0.0f, offsets 0
        for (int j = 0; j < n; j++) {
            g_terms[kA + j] = (j < cA) ? st8[sA + j] : zero;
            g_terms[kB + j] = (j < cB) ? st8[sB + j] : zero;
        }
        uint2 pd;
        pd.x = (unsigned int)kA | ((unsigned int)kB << 16);
        pd.y = (unsigned int)meta;
        g_pairs[p] = pd;
    }
}

// ---------------------------------------------------------------------------
// Main: 2 edges per 128-thread block; 64 threads/edge, one channel pair per
// thread, packed f32x2. Two output rows processed as interleaved independent
// streams per iteration (uniform trip count via padding). Terms from constant
// memory (LDC broadcast, zero L1TEX cost). Each output element written once
// (the lone duplicated row writes the identical value twice).
// ---------------------------------------------------------------------------
__global__ __launch_bounds__(THREADS)
void tp_kernel(const float* __restrict__ x,
               const float* __restrict__ y,
               float* __restrict__ out)
{
    __shared__ __align__(16) float sx[EPB * DIM_IN * CH];   // 16 KB
    __shared__ __align__(16) float sy[EPB * DIM_IN * CH];   // 16 KB

    const int t    = threadIdx.x;
    const int sub  = t >> 6;
    const int lane = t & 63;
    const long long ebase = (long long)blockIdx.x * EPB;

    const float4* x4 = (const float4*)(x + ebase * (DIM_IN * CH));
    const float4* y4 = (const float4*)(y + ebase * (DIM_IN * CH));
#pragma unroll
    for (int i = 0; i < (EPB * DIM_IN * CH / 4) / THREADS; i++) {
        ((float4*)sx)[t + i * THREADS] = x4[t + i * THREADS];
        ((float4*)sy)[t + i * THREADS] = y4[t + i * THREADS];
    }
    __syncthreads();

    const char* sxb = (const char*)(sx + sub * (DIM_IN * CH)) + lane * 8;
    const char* syb = (const char*)(sy + sub * (DIM_IN * CH)) + lane * 8;
    float* outb = out + (ebase + sub) * (DIM_OUT * CH) + lane * 2;

#pragma unroll 1
    for (int p = 0; p < NPAIRS; p++) {
        uint2 pd = c_pairs[p];
        const int kA = pd.x & 0xFFFFu;
        const int kB = pd.x >> 16;
        const int n  = pd.y & 0xFFu;
        const int oA = (pd.y >> 8) & 0xFFu;
        const int oB = (pd.y >> 16) & 0xFFu;

        unsigned long long accA = 0ull, accB = 0ull;
#pragma unroll 2
        for (int j = 0; j < n; j++) {
            uint2 ta = c_terms[kA + j];
            uint2 tb = c_terms[kB + j];
            unsigned int oxA = ta.x & 0xFFFFu, oyA = ta.x >> 16;
            unsigned int oxB = tb.x & 0xFFFFu, oyB = tb.x >> 16;
            unsigned long long cgA, cgB;
            asm("mov.b64 %0, {%1, %1};" : "=l"(cgA) : "r"(ta.y));
            asm("mov.b64 %0, {%1, %1};" : "=l"(cgB) : "r"(tb.y));
            unsigned long long xvA = *(const unsigned long long*)(sxb + oxA);
            unsigned long long yvA = *(const unsigned long long*)(syb + oyA);
            unsigned long long xvB = *(const unsigned long long*)(sxb + oxB);
            unsigned long long yvB = *(const unsigned long long*)(syb + oyB);
            unsigned long long pA, pB;
            asm("mul.rn.f32x2 %0, %1, %2;" : "=l"(pA) : "l"(xvA), "l"(yvA));
            asm("mul.rn.f32x2 %0, %1, %2;" : "=l"(pB) : "l"(xvB), "l"(yvB));
            asm("fma.rn.f32x2 %0, %1, %2, %3;"
                : "=l"(accA) : "l"(pA), "l"(cgA), "l"(accA));
            asm("fma.rn.f32x2 %0, %1, %2, %3;"
                : "=l"(accB) : "l"(pB), "l"(cgB), "l"(accB));
        }
        *(unsigned long long*)(outb + oA * CH) = accA;
        *(unsigned long long*)(outb + oB * CH) = accB;
    }
}

// ---------------------------------------------------------------------------
// Inputs (metadata order): x f32 [N,16,128], y f32 [N,16,128],
//                          mu1 i32 [nnz], mu2 i32 [nnz], mu3 i32 [nnz], cg f32 [nnz]
// Output: f32 [N,99,128]
// ---------------------------------------------------------------------------
extern "C" void kernel_launch(void* const* d_in, const int* in_sizes, int n_in,
                              void* d_out, int out_size)
{
    const float* x   = (const float*)d_in[0];
    const float* y   = (const float*)d_in[1];
    const int*   mu1 = (const int*)d_in[2];
    const int*   mu2 = (const int*)d_in[3];
    const int*   mu3 = (const int*)d_in[4];
    const float* cg  = (const float*)d_in[5];

    int nnz = in_sizes[2];
    if (nnz > MAX_NNZ) nnz = MAX_NNZ;   // capacity guard (actual nnz ~350)
    int N = in_sizes[0] / (DIM_IN * CH);
    int nBlocks = (N + EPB - 1) / EPB;

    prep_kernel<<<1, 1024>>>(mu1, mu2, mu3, cg, nnz);

    // D2D copies of prepared tables into constant memory (graph-legal memcpys)
    void* gt_addr = nullptr;
    void* gp_addr = nullptr;
    cudaGetSymbolAddress(&gt_addr, g_terms);
    cudaGetSymbolAddress(&gp_addr, g_pairs);
    cudaMemcpyToSymbolAsync(c_terms, gt_addr, sizeof(uint2) * MAX_PADDED, 0,
                            cudaMemcpyDeviceToDevice, 0);
    cudaMemcpyToSymbolAsync(c_pairs, gp_addr, sizeof(uint2) * NPAIRS, 0,
                            cudaMemcpyDeviceToDevice, 0);

    tp_kernel<<<nBlocks, THREADS>>>(x, y, (float*)d_out);
}

// round 10
// speedup vs baseline: 2.8288x; 2.8288x over previous
#include <cuda_runtime.h>
#include <stdint.h>

#define DIM_IN 16
#define CH 128
#define DIM_OUT 99
#define MAX_NNZ 512
#define MAX_PADDED 1024
#define NPAIRS ((DIM_OUT + 1) / 2)   // 50
#define EPB 2
#define THREADS (EPB * 64)

// 8-byte term: .x = ox | (oy<<16) (u16 byte offsets into 8 KB row block), .y = cg
__device__ uint2 g_terms[MAX_PADDED];
__device__ uint2 g_pairs[NPAIRS];
// pair: .x = kA | (kB<<16) ; .y = n | (oA<<8) | (oB<<16)

__constant__ uint2 c_terms[MAX_PADDED];
__constant__ uint2 c_pairs[NPAIRS];

// ---------------------------------------------------------------------------
// Prep: CSR-sort terms by mu3 (stable), order rows by count desc (stable,
// computed via PARALLEL per-row rank — no serial sort), pair adjacent rows,
// zero-pad shorter row of each pair. All deterministic.
// ---------------------------------------------------------------------------
__global__ void prep_kernel(const int* __restrict__ mu1,
                            const int* __restrict__ mu2,
                            const int* __restrict__ mu3,
                            const float* __restrict__ cg,
                            int nnz)
{
    __shared__ int   sm3[MAX_NNZ];
    __shared__ uint2 st8[MAX_NNZ];       // CSR-sorted compact terms
    __shared__ int   start[DIM_OUT + 1]; // row starts
    __shared__ int   cnt[DIM_OUT];       // row counts
    __shared__ int   order[DIM_OUT];     // rows sorted by count desc (stable)
    __shared__ int   pkA[NPAIRS], pmeta[NPAIRS];
    int t = threadIdx.x;

    if (t < DIM_OUT) cnt[t] = 0;
    __syncthreads();

    for (int k = t; k < nnz; k += blockDim.x) {
        int m = mu3[k];
        sm3[k] = m;
        atomicAdd(&cnt[m], 1);
    }
    __syncthreads();

    if (t == 0) {
        int s = 0;
        for (int o = 0; o < DIM_OUT; o++) { start[o] = s; s += cnt[o]; }
        start[DIM_OUT] = s;
    }
    __syncthreads();

    // stable scatter into CSR (rank = #earlier terms with same mu3)
    for (int k = t; k < nnz; k += blockDim.x) {
        int m = sm3[k];
        int rank = 0;
        for (int j = 0; j < k; j++) rank += (sm3[j] == m);
        unsigned int ox = (unsigned int)mu1[k] * (CH * 4u);
        unsigned int oy = (unsigned int)mu2[k] * (CH * 4u);
        uint2 tm;
        tm.x = ox | (oy << 16);
        tm.y = __float_as_uint(cg[k]);
        st8[start[m] + rank] = tm;
    }
    __syncthreads();

    // parallel rank: rows ordered by (count desc, row id asc) — deterministic
    if (t < DIM_OUT) {
        int c = cnt[t];
        int rk = 0;
        for (int r = 0; r < DIM_OUT; r++) {
            int cr = cnt[r];
            rk += (cr > c) || (cr == c && r < t);
        }
        order[rk] = t;
    }
    __syncthreads();

    // thread0: tiny serial prefix over 50 pairs
    if (t == 0) {
        int base = 0;
        for (int p = 0; p < NPAIRS; p++) {
            int rA = order[2 * p];
            int rB = (2 * p + 1 < DIM_OUT) ? order[2 * p + 1] : rA;
            int cA = cnt[rA], cB = cnt[rB];
            int n  = cA > cB ? cA : cB;
            pkA[p]   = base;
            pmeta[p] = n | (rA << 8) | (rB << 16);
            base += 2 * n;
        }
    }
    __syncthreads();

    // parallel emit of padded term table + pair descriptors (n <= ~16)
    for (int p = t; p < NPAIRS; p += blockDim.x) {
        int meta = pmeta[p];
        int n  = meta & 0xFF;
        int rA = (meta >> 8) & 0xFF;
        int rB = (meta >> 16) & 0xFF;
        int kA = pkA[p];
        int kB = kA + n;
        int sA = start[rA], cA = cnt[rA];
        int sB = start[rB], cB = cnt[rB];
        uint2 zero; zero.x = 0u; zero.y = 0u;   // cg = +0.0f, offsets 0
        for (int j = 0; j < n; j++) {
            g_terms[kA + j] = (j < cA) ? st8[sA + j] : zero;
            g_terms[kB + j] = (j < cB) ? st8[sB + j] : zero;
        }
        uint2 pd;
        pd.x = (unsigned int)kA | ((unsigned int)kB << 16);
        pd.y = (unsigned int)meta;
        g_pairs[p] = pd;
    }
}

// ---------------------------------------------------------------------------
// Main (unchanged from best measured kernel, 70.2us): 2 edges per 128-thread
// block; 64 threads/edge, one channel pair per thread, packed f32x2. Two
// output rows processed as interleaved independent streams per iteration.
// Terms from constant memory (LDC broadcast). Each output element written
// once (the lone duplicated row writes the identical value twice).
// ---------------------------------------------------------------------------
__global__ __launch_bounds__(THREADS)
void tp_kernel(const float* __restrict__ x,
               const float* __restrict__ y,
               float* __restrict__ out)
{
    __shared__ __align__(16) float sx[EPB * DIM_IN * CH];   // 16 KB
    __shared__ __align__(16) float sy[EPB * DIM_IN * CH];   // 16 KB

    const int t    = threadIdx.x;
    const int sub  = t >> 6;
    const int lane = t & 63;
    const long long ebase = (long long)blockIdx.x * EPB;

    const float4* x4 = (const float4*)(x + ebase * (DIM_IN * CH));
    const float4* y4 = (const float4*)(y + ebase * (DIM_IN * CH));
#pragma unroll
    for (int i = 0; i < (EPB * DIM_IN * CH / 4) / THREADS; i++) {
        ((float4*)sx)[t + i * THREADS] = x4[t + i * THREADS];
        ((float4*)sy)[t + i * THREADS] = y4[t + i * THREADS];
    }
    __syncthreads();

    const char* sxb = (const char*)(sx + sub * (DIM_IN * CH)) + lane * 8;
    const char* syb = (const char*)(sy + sub * (DIM_IN * CH)) + lane * 8;
    float* outb = out + (ebase + sub) * (DIM_OUT * CH) + lane * 2;

#pragma unroll 1
    for (int p = 0; p < NPAIRS; p++) {
        uint2 pd = c_pairs[p];
        const int kA = pd.x & 0xFFFFu;
        const int kB = pd.x >> 16;
        const int n  = pd.y & 0xFFu;
        const int oA = (pd.y >> 8) & 0xFFu;
        const int oB = (pd.y >> 16) & 0xFFu;

        unsigned long long accA = 0ull, accB = 0ull;
#pragma unroll 2
        for (int j = 0; j < n; j++) {
            uint2 ta = c_terms[kA + j];
            uint2 tb = c_terms[kB + j];
            unsigned int oxA = ta.x & 0xFFFFu, oyA = ta.x >> 16;
            unsigned int oxB = tb.x & 0xFFFFu, oyB = tb.x >> 16;
            unsigned long long cgA, cgB;
            asm("mov.b64 %0, {%1, %1};" : "=l"(cgA) : "r"(ta.y));
            asm("mov.b64 %0, {%1, %1};" : "=l"(cgB) : "r"(tb.y));
            unsigned long long xvA = *(const unsigned long long*)(sxb + oxA);
            unsigned long long yvA = *(const unsigned long long*)(syb + oyA);
            unsigned long long xvB = *(const unsigned long long*)(sxb + oxB);
            unsigned long long yvB = *(const unsigned long long*)(syb + oyB);
            unsigned long long pA, pB;
            asm("mul.rn.f32x2 %0, %1, %2;" : "=l"(pA) : "l"(xvA), "l"(yvA));
            asm("mul.rn.f32x2 %0, %1, %2;" : "=l"(pB) : "l"(xvB), "l"(yvB));
            asm("fma.rn.f32x2 %0, %1, %2, %3;"
                : "=l"(accA) : "l"(pA), "l"(cgA), "l"(accA));
            asm("fma.rn.f32x2 %0, %1, %2, %3;"
                : "=l"(accB) : "l"(pB), "l"(cgB), "l"(accB));
        }
        *(unsigned long long*)(outb + oA * CH) = accA;
        *(unsigned long long*)(outb + oB * CH) = accB;
    }
}

// ---------------------------------------------------------------------------
// Inputs (metadata order): x f32 [N,16,128], y f32 [N,16,128],
//                          mu1 i32 [nnz], mu2 i32 [nnz], mu3 i32 [nnz], cg f32 [nnz]
// Output: f32 [N,99,128]
// ---------------------------------------------------------------------------
extern "C" void kernel_launch(void* const* d_in, const int* in_sizes, int n_in,
                              void* d_out, int out_size)
{
    const float* x   = (const float*)d_in[0];
    const float* y   = (const float*)d_in[1];
    const int*   mu1 = (const int*)d_in[2];
    const int*   mu2 = (const int*)d_in[3];
    const int*   mu3 = (const int*)d_in[4];
    const float* cg  = (const float*)d_in[5];

    int nnz = in_sizes[2];
    if (nnz > MAX_NNZ) nnz = MAX_NNZ;   // capacity guard (actual nnz ~350)
    int N = in_sizes[0] / (DIM_IN * CH);
    int nBlocks = (N + EPB - 1) / EPB;

    prep_kernel<<<1, 1024>>>(mu1, mu2, mu3, cg, nnz);

    // D2D copies of prepared tables into constant memory (graph-legal memcpys)
    void* gt_addr = nullptr;
    void* gp_addr = nullptr;
    cudaGetSymbolAddress(&gt_addr, g_terms);
    cudaGetSymbolAddress(&gp_addr, g_pairs);
    cudaMemcpyToSymbolAsync(c_terms, gt_addr, sizeof(uint2) * MAX_PADDED, 0,
                            cudaMemcpyDeviceToDevice, 0);
    cudaMemcpyToSymbolAsync(c_pairs, gp_addr, sizeof(uint2) * NPAIRS, 0,
                            cudaMemcpyDeviceToDevice, 0);

    tp_kernel<<<nBlocks, THREADS>>>(x, y, (float*)d_out);
}

// round 11
// speedup vs baseline: 2.9803x; 1.0536x over previous
#include <cuda_runtime.h>
#include <stdint.h>

#define DIM_IN 16
#define CH 128
#define DIM_OUT 99
#define MAX_NNZ 512
#define MAX_PADDED 1024
#define NGROUPS ((DIM_OUT + 3) / 4)   // 25 groups of 4 rows
#define EPB 2
#define THREADS (EPB * 64)

// 16-byte term (ulonglong2): .x = ox | (oy<<16) in low 32 (u16 byte offsets
// into the 8 KB row block), .y = {cg, cg} pre-packed for f32x2 FMA.
__device__ ulonglong2 g_terms[MAX_PADDED];
__device__ uint2      g_groups[NGROUPS];
// group: .x = kG | (n<<16) | (rowA<<24) ; .y = rowB | (rowC<<8) | (rowD<<16)

__constant__ ulonglong2 c_terms[MAX_PADDED];
__constant__ uint2      c_groups[NGROUPS];

// ---------------------------------------------------------------------------
// Prep: CSR-sort terms by mu3 (stable), order rows by count desc (parallel
// rank, deterministic), group rows in 4s, zero-pad each row to group max.
// ---------------------------------------------------------------------------
__global__ void prep_kernel(const int* __restrict__ mu1,
                            const int* __restrict__ mu2,
                            const int* __restrict__ mu3,
                            const float* __restrict__ cg,
                            int nnz)
{
    __shared__ int   sm3[MAX_NNZ];
    __shared__ uint2 st8[MAX_NNZ];       // CSR-sorted compact terms
    __shared__ int   start[DIM_OUT + 1];
    __shared__ int   cnt[DIM_OUT];
    __shared__ int   order[DIM_OUT];
    __shared__ int   gk[NGROUPS], gn[NGROUPS];
    int t = threadIdx.x;

    if (t < DIM_OUT) cnt[t] = 0;
    __syncthreads();

    for (int k = t; k < nnz; k += blockDim.x) {
        int m = mu3[k];
        sm3[k] = m;
        atomicAdd(&cnt[m], 1);
    }
    __syncthreads();

    if (t == 0) {
        int s = 0;
        for (int o = 0; o < DIM_OUT; o++) { start[o] = s; s += cnt[o]; }
        start[DIM_OUT] = s;
    }
    __syncthreads();

    // stable scatter into CSR (rank = #earlier terms with same mu3)
    for (int k = t; k < nnz; k += blockDim.x) {
        int m = sm3[k];
        int rank = 0;
        for (int j = 0; j < k; j++) rank += (sm3[j] == m);
        unsigned int ox = (unsigned int)mu1[k] * (CH * 4u);
        unsigned int oy = (unsigned int)mu2[k] * (CH * 4u);
        uint2 tm;
        tm.x = ox | (oy << 16);
        tm.y = __float_as_uint(cg[k]);
        st8[start[m] + rank] = tm;
    }
    __syncthreads();

    // parallel rank: rows ordered by (count desc, row id asc) — deterministic
    if (t < DIM_OUT) {
        int c = cnt[t];
        int rk = 0;
        for (int r = 0; r < DIM_OUT; r++) {
            int cr = cnt[r];
            rk += (cr > c) || (cr == c && r < t);
        }
        order[rk] = t;
    }
    __syncthreads();

    // thread0: tiny serial prefix over 25 groups (counts sorted desc, so the
    // group's first row carries its max count)
    if (t == 0) {
        int base = 0;
        for (int g = 0; g < NGROUPS; g++) {
            int i0 = 4 * g;
            int rA = order[i0];
            int rB = order[(i0 + 1 < DIM_OUT) ? i0 + 1 : DIM_OUT - 1];
            int rC = order[(i0 + 2 < DIM_OUT) ? i0 + 2 : DIM_OUT - 1];
            int rD = order[(i0 + 3 < DIM_OUT) ? i0 + 3 : DIM_OUT - 1];
            int n  = cnt[rA];
            gk[g] = base;
            gn[g] = n;
            uint2 gd;
            gd.x = (unsigned int)base | ((unsigned int)n << 16)
                 | ((unsigned int)rA << 24);
            gd.y = (unsigned int)rB | ((unsigned int)rC << 8)
                 | ((unsigned int)rD << 16);
            g_groups[g] = gd;
            base += 4 * n;
        }
    }
    __syncthreads();

    // parallel emit of padded 16-byte term streams (one thread per row slot)
    for (int i = t; i < 4 * NGROUPS; i += blockDim.x) {
        int g = i >> 2;
        int s = i & 3;
        int oi = (i < DIM_OUT) ? i : DIM_OUT - 1;
        int row = order[oi];
        int n   = gn[g];
        int kS  = gk[g] + s * n;
        int sR = start[row], cR = cnt[row];
        for (int j = 0; j < n; j++) {
            ulonglong2 e;
            if (j < cR) {
                uint2 tm = st8[sR + j];
                e.x = (unsigned long long)tm.x;
                e.y = ((unsigned long long)tm.y << 32) | (unsigned long long)tm.y;
            } else {
                e.x = 0ull;
                e.y = 0ull;      // cg = {+0,+0}: exact no-op FMA
            }
            g_terms[kS + j] = e;
        }
    }
}

// ---------------------------------------------------------------------------
// Main: 2 edges per 128-thread block; 64 threads/edge, one channel pair per
// thread, packed f32x2. FOUR output rows processed as interleaved independent
// streams per group (uniform trip count via padding). Terms from constant
// memory (LDC.128 broadcast, cg pre-duplicated). Each real output element
// written once; the duplicated tail row rewrites an identical value.
// ---------------------------------------------------------------------------
__global__ __launch_bounds__(THREADS, 5)
void tp_kernel(const float* __restrict__ x,
               const float* __restrict__ y,
               float* __restrict__ out)
{
    __shared__ __align__(16) float sx[EPB * DIM_IN * CH];   // 16 KB
    __shared__ __align__(16) float sy[EPB * DIM_IN * CH];   // 16 KB

    const int t    = threadIdx.x;
    const int sub  = t >> 6;
    const int lane = t & 63;
    const long long ebase = (long long)blockIdx.x * EPB;

    const float4* x4 = (const float4*)(x + ebase * (DIM_IN * CH));
    const float4* y4 = (const float4*)(y + ebase * (DIM_IN * CH));
#pragma unroll
    for (int i = 0; i < (EPB * DIM_IN * CH / 4) / THREADS; i++) {
        ((float4*)sx)[t + i * THREADS] = x4[t + i * THREADS];
        ((float4*)sy)[t + i * THREADS] = y4[t + i * THREADS];
    }
    __syncthreads();

    const char* sxb = (const char*)(sx + sub * (DIM_IN * CH)) + lane * 8;
    const char* syb = (const char*)(sy + sub * (DIM_IN * CH)) + lane * 8;
    float* outb = out + (ebase + sub) * (DIM_OUT * CH) + lane * 2;

#pragma unroll 1
    for (int g = 0; g < NGROUPS; g++) {
        uint2 gd = c_groups[g];
        const int kG = gd.x & 0xFFFFu;
        const int n  = (gd.x >> 16) & 0xFFu;
        const int oA = gd.x >> 24;
        const int oB = gd.y & 0xFFu;
        const int oC = (gd.y >> 8) & 0xFFu;
        const int oD = (gd.y >> 16) & 0xFFu;

        const ulonglong2* tA = c_terms + kG;
        const ulonglong2* tB = tA + n;
        const ulonglong2* tC = tB + n;
        const ulonglong2* tD = tC + n;

        unsigned long long accA = 0ull, accB = 0ull;
        unsigned long long accC = 0ull, accD = 0ull;
#pragma unroll 2
        for (int j = 0; j < n; j++) {
            ulonglong2 ta = tA[j];
            ulonglong2 tb = tB[j];
            ulonglong2 tc = tC[j];
            ulonglong2 td = tD[j];
            unsigned int ma = (unsigned int)ta.x;
            unsigned int mb = (unsigned int)tb.x;
            unsigned int mc = (unsigned int)tc.x;
            unsigned int md = (unsigned int)td.x;
            unsigned long long xvA = *(const unsigned long long*)(sxb + (ma & 0xFFFFu));
            unsigned long long yvA = *(const unsigned long long*)(syb + (ma >> 16));
            unsigned long long xvB = *(const unsigned long long*)(sxb + (mb & 0xFFFFu));
            unsigned long long yvB = *(const unsigned long long*)(syb + (mb >> 16));
            unsigned long long xvC = *(const unsigned long long*)(sxb + (mc & 0xFFFFu));
            unsigned long long yvC = *(const unsigned long long*)(syb + (mc >> 16));
            unsigned long long xvD = *(const unsigned long long*)(sxb + (md & 0xFFFFu));
            unsigned long long yvD = *(const unsigned long long*)(syb + (md >> 16));
            unsigned long long pA, pB, pC, pD;
            asm("mul.rn.f32x2 %0, %1, %2;" : "=l"(pA) : "l"(xvA), "l"(yvA));
            asm("mul.rn.f32x2 %0, %1, %2;" : "=l"(pB) : "l"(xvB), "l"(yvB));
            asm("mul.rn.f32x2 %0, %1, %2;" : "=l"(pC) : "l"(xvC), "l"(yvC));
            asm("mul.rn.f32x2 %0, %1, %2;" : "=l"(pD) : "l"(xvD), "l"(yvD));
            asm("fma.rn.f32x2 %0, %1, %2, %3;"
                : "=l"(accA) : "l"(pA), "l"(ta.y), "l"(accA));
            asm("fma.rn.f32x2 %0, %1, %2, %3;"
                : "=l"(accB) : "l"(pB), "l"(tb.y), "l"(accB));
            asm("fma.rn.f32x2 %0, %1, %2, %3;"
                : "=l"(accC) : "l"(pC), "l"(tc.y), "l"(accC));
            asm("fma.rn.f32x2 %0, %1, %2, %3;"
                : "=l"(accD) : "l"(pD), "l"(td.y), "l"(accD));
        }
        *(unsigned long long*)(outb + oA * CH) = accA;
        *(unsigned long long*)(outb + oB * CH) = accB;
        *(unsigned long long*)(outb + oC * CH) = accC;
        *(unsigned long long*)(outb + oD * CH) = accD;
    }
}

// ---------------------------------------------------------------------------
// Inputs (metadata order): x f32 [N,16,128], y f32 [N,16,128],
//                          mu1 i32 [nnz], mu2 i32 [nnz], mu3 i32 [nnz], cg f32 [nnz]
// Output: f32 [N,99,128]
// ---------------------------------------------------------------------------
extern "C" void kernel_launch(void* const* d_in, const int* in_sizes, int n_in,
                              void* d_out, int out_size)
{
    const float* x   = (const float*)d_in[0];
    const float* y   = (const float*)d_in[1];
    const int*   mu1 = (const int*)d_in[2];
    const int*   mu2 = (const int*)d_in[3];
    const int*   mu3 = (const int*)d_in[4];
    const float* cg  = (const float*)d_in[5];

    int nnz = in_sizes[2];
    if (nnz > MAX_NNZ) nnz = MAX_NNZ;   // capacity guard (actual nnz ~350)
    int N = in_sizes[0] / (DIM_IN * CH);
    int nBlocks = (N + EPB - 1) / EPB;

    prep_kernel<<<1, 1024>>>(mu1, mu2, mu3, cg, nnz);

    // D2D copies of prepared tables into constant memory (graph-legal memcpys)
    void* gt_addr = nullptr;
    void* gg_addr = nullptr;
    cudaGetSymbolAddress(&gt_addr, g_terms);
    cudaGetSymbolAddress(&gg_addr, g_groups);
    cudaMemcpyToSymbolAsync(c_terms, gt_addr, sizeof(ulonglong2) * MAX_PADDED, 0,
                            cudaMemcpyDeviceToDevice, 0);
    cudaMemcpyToSymbolAsync(c_groups, gg_addr, sizeof(uint2) * NGROUPS, 0,
                            cudaMemcpyDeviceToDevice, 0);

    tp_kernel<<<nBlocks, THREADS>>>(x, y, (float*)d_out);
}